// round 3
// baseline (speedup 1.0000x reference)
#include <cuda_runtime.h>

// out[n][d] = (x[n]==0 ? 0 : W[x[n]][d]) + PE(n,d)
// PE(n,d): pos = n+1; even d -> cos(pos * 10000^{-d/D});
//          odd d  -> sin(pos * 10000^{-(d+1)/D})
// Only even exponents e appear: e in {0,2,...,1024} -> 513 distinct frequencies.
//
// Two kernels:
//  1) setup: for every (chunk c, even exponent e) compute exact-in-double
//     seed (sin,cos)((128c+1) * w_e) and the unit rotation (sin,cos)(w_e).
//  2) main: per 128-row chunk, load seeds (no transcendentals at all),
//     stream gather+add+store, advancing PE by a 2x2 FMA rotation per row.
// Drift is bounded by 128 rotation steps (same as the R1 passing kernel).

#define D_DIM   1024
#define TPB     256          // D/4 threads: one float4 lane set per thread
#define ROWS    128          // rows per chunk (recurrence length)
#define MAXN    131072
#define NCHUNK  (MAXN / ROWS)   // 1024
#define NE      513             // even exponents 0..1024

// scratch tables (allocation-free rule: __device__ globals)
__device__ float2 g_seed[NCHUNK * NE];  // [c][e/2] = (sin, cos)((128c+1)*w_e)  ~4.2MB
__device__ float2 g_rot[NE];            // [e/2]    = (sin, cos)(w_e)

__global__ void pe_setup_kernel(int nchunks)
{
    int gid = blockIdx.x * blockDim.x + threadIdx.x;
    int total = nchunks * NE;
    if (gid >= total) return;
    int c  = gid / NE;
    int ie = gid - c * NE;          // e/2
    int e  = ie * 2;

    const double LOG1E4  = 9.210340371976184;     // ln(10000)
    const double TWO_PI  = 6.283185307179586476925287;

    double w = exp(-(double)e * (LOG1E4 / (double)D_DIM));
    double pos0 = (double)(c * ROWS + 1);
    double ang  = pos0 * w;
    ang -= TWO_PI * floor(ang / TWO_PI);
    double ss, cc;
    sincos(ang, &ss, &cc);
    g_seed[gid] = make_float2((float)ss, (float)cc);

    if (c == 0) {
        double sw, cw;
        sincos(w, &sw, &cw);
        g_rot[ie] = make_float2((float)sw, (float)cw);
    }
}

__global__ __launch_bounds__(TPB)
void pe_embed_kernel(const int* __restrict__ x,
                     const float* __restrict__ W,
                     float* __restrict__ out,
                     int N)
{
    __shared__ int sx[ROWS];

    const int chunk = blockIdx.x;
    const int n0 = chunk * ROWS;
    const int t  = threadIdx.x;

    if (t < ROWS) {
        int n = n0 + t;
        sx[t] = (n < N) ? x[n] : 0;
    }

    // states m=0..2 use exponent e = 4t + 2m  -> table index ie = 2t + m
    float s[3], c[3], sw[3], cw[3];
    {
        const float2* __restrict__ seed = g_seed + (long)chunk * NE;
#pragma unroll
        for (int m = 0; m < 3; m++) {
            int ie = 2 * t + m;
            float2 sc = __ldg(&seed[ie]);
            float2 rt = __ldg(&g_rot[ie]);
            s[m] = sc.x;  c[m] = sc.y;
            sw[m] = rt.x; cw[m] = rt.y;
        }
    }
    __syncthreads();

    const float4* __restrict__ Wv = (const float4*)W;
    float4* outv = (float4*)out;

    const int nr = (N - n0 < ROWS) ? (N - n0) : ROWS;
    const long obase = (long)n0 * (D_DIM / 4) + t;

#pragma unroll 4
    for (int r = 0; r < nr; r++) {
        int idx = sx[r];
        float4 e = make_float4(0.f, 0.f, 0.f, 0.f);
        if (idx != 0) {                 // padding_idx row contributes zero
            e = __ldg(&Wv[(long)idx * (D_DIM / 4) + t]);
        }
        float4 o;
        o.x = e.x + c[0];
        o.y = e.y + s[1];
        o.z = e.z + c[1];
        o.w = e.w + s[2];
        // streaming store: keep the 512MB output from evicting W rows in L2
        __stcs(&outv[obase + (long)r * (D_DIM / 4)], o);

        // advance all three states by one row: (s,c) <- rot(w) * (s,c)
#pragma unroll
        for (int m = 0; m < 3; m++) {
            float ns = fmaf(s[m], cw[m],  c[m] * sw[m]);
            float nc = fmaf(c[m], cw[m], -s[m] * sw[m]);
            s[m] = ns;
            c[m] = nc;
        }
    }
}

extern "C" void kernel_launch(void* const* d_in, const int* in_sizes, int n_in,
                              void* d_out, int out_size)
{
    const int*   x;
    const float* W;
    int N;
    if (in_sizes[0] < in_sizes[1]) {
        x = (const int*)d_in[0];  W = (const float*)d_in[1];  N = in_sizes[0];
    } else {
        x = (const int*)d_in[1];  W = (const float*)d_in[0];  N = in_sizes[1];
    }
    int nchunks = (N + ROWS - 1) / ROWS;
    if (nchunks > NCHUNK) nchunks = NCHUNK;   // table capacity (N<=131072 here)

    int setup_total  = nchunks * NE;
    int setup_blocks = (setup_total + 255) / 256;
    pe_setup_kernel<<<setup_blocks, 256>>>(nchunks);

    pe_embed_kernel<<<nchunks, TPB>>>(x, W, (float*)d_out, N);
}

// round 4
// speedup vs baseline: 1.4722x; 1.4722x over previous
#include <cuda_runtime.h>

// out[n][d] = (x[n]==0 ? 0 : W[x[n]][d]) + PE(n,d)
// Even exponents e in {0,2,...,1024} -> 513 distinct frequencies (NE).
//
// setup: 16.4K threads; each computes ONE DP exp + two DP sincos, then emits
//        32 chunk seeds via a DP rotation recurrence (step = 128*w). ~5us.
// main:  per 128-row chunk: seeds from L2 table, then gather+add+store with
//        G=8 explicit load batching for deep MLP. PE advances by fp32 rotation
//        (drift bounded by 128 steps, same numerics as the 198us passing run).

#define D_DIM   1024
#define TPB     256
#define ROWS    128
#define MAXN    131072
#define NCHUNK  (MAXN / ROWS)    // 1024
#define NE      513              // even exponents 0..1024
#define CB      32               // chunks per setup thread
#define G       8                // rows batched per inner iteration

__device__ float2 g_seed[NCHUNK * NE];  // [c][e/2] = (sin,cos)((128c+1)*w_e)
__device__ float2 g_rot[NE];            // [e/2]    = (sin,cos)(w_e)

__global__ void pe_setup_kernel(int nchunks)
{
    int gid = blockIdx.x * blockDim.x + threadIdx.x;
    const int nth_per_ie = NCHUNK / CB;            // 32
    if (gid >= NE * nth_per_ie) return;
    int ie = gid / nth_per_ie;
    int cb = gid - ie * nth_per_ie;
    int c0 = cb * CB;

    const double LOG1E4 = 9.210340371976184;       // ln(10000)
    double w = exp(-(double)(2 * ie) * (LOG1E4 / (double)D_DIM));

    // chunk-step rotation: angle = 128*w  (DP sincos does its own range reduction)
    double sstep, cstep;
    sincos((double)ROWS * w, &sstep, &cstep);

    // seed at chunk c0: angle = (128*c0 + 1) * w
    double s, c;
    sincos((double)(c0 * ROWS + 1) * w, &s, &c);

    if (cb == 0) {
        double sw, cw;
        sincos(w, &sw, &cw);
        g_rot[ie] = make_float2((float)sw, (float)cw);
    }

#pragma unroll 4
    for (int j = 0; j < CB; j++) {
        int cidx = c0 + j;
        if (cidx < nchunks)
            g_seed[(long)cidx * NE + ie] = make_float2((float)s, (float)c);
        double ns = s * cstep + c * sstep;         // DP advance: negligible drift
        double nc = c * cstep - s * sstep;
        s = ns; c = nc;
    }
}

__global__ __launch_bounds__(TPB, 3)
void pe_embed_kernel(const int* __restrict__ x,
                     const float* __restrict__ W,
                     float* __restrict__ out,
                     int N)
{
    __shared__ int sx[ROWS];

    const int chunk = blockIdx.x;
    const int n0 = chunk * ROWS;
    const int t  = threadIdx.x;

    if (t < ROWS) {
        int n = n0 + t;
        sx[t] = (n < N) ? x[n] : 0;
    }

    // states m=0..2 use exponent e = 4t + 2m -> table index ie = 2t + m
    float s[3], c[3], sw[3], cw[3];
    {
        const float2* __restrict__ seed = g_seed + (long)chunk * NE;
#pragma unroll
        for (int m = 0; m < 3; m++) {
            int ie = 2 * t + m;
            float2 sc = __ldg(&seed[ie]);
            float2 rt = __ldg(&g_rot[ie]);
            s[m] = sc.x;  c[m] = sc.y;
            sw[m] = rt.x; cw[m] = rt.y;
        }
    }
    __syncthreads();

    const float4* __restrict__ Wv = (const float4*)W;
    float4* outv = (float4*)out;

    const int nr = (N - n0 < ROWS) ? (N - n0) : ROWS;
    const long obase = (long)n0 * (D_DIM / 4) + t;

    if (nr == ROWS) {
        // fast path: batch G row-gathers before compute/store -> deep MLP
        for (int rb = 0; rb < ROWS; rb += G) {
            int   idx[G];
            float4 e[G];
#pragma unroll
            for (int j = 0; j < G; j++) idx[j] = sx[rb + j];
#pragma unroll
            for (int j = 0; j < G; j++)   // unconditional: row 0 is valid memory
                e[j] = __ldg(&Wv[(long)idx[j] * (D_DIM / 4) + t]);
#pragma unroll
            for (int j = 0; j < G; j++) {
                float msk = (idx[j] == 0) ? 0.f : 1.f;   // padding row -> zero
                float4 o;
                o.x = fmaf(e[j].x, msk, c[0]);
                o.y = fmaf(e[j].y, msk, s[1]);
                o.z = fmaf(e[j].z, msk, c[1]);
                o.w = fmaf(e[j].w, msk, s[2]);
                __stcs(&outv[obase + (long)(rb + j) * (D_DIM / 4)], o);
#pragma unroll
                for (int m = 0; m < 3; m++) {
                    float ns = fmaf(s[m], cw[m],  c[m] * sw[m]);
                    float nc = fmaf(c[m], cw[m], -s[m] * sw[m]);
                    s[m] = ns; c[m] = nc;
                }
            }
        }
    } else {
        for (int r = 0; r < nr; r++) {
            int idx = sx[r];
            float4 e = make_float4(0.f, 0.f, 0.f, 0.f);
            if (idx != 0) e = __ldg(&Wv[(long)idx * (D_DIM / 4) + t]);
            float4 o;
            o.x = e.x + c[0];
            o.y = e.y + s[1];
            o.z = e.z + c[1];
            o.w = e.w + s[2];
            __stcs(&outv[obase + (long)r * (D_DIM / 4)], o);
#pragma unroll
            for (int m = 0; m < 3; m++) {
                float ns = fmaf(s[m], cw[m],  c[m] * sw[m]);
                float nc = fmaf(c[m], cw[m], -s[m] * sw[m]);
                s[m] = ns; c[m] = nc;
            }
        }
    }
}

extern "C" void kernel_launch(void* const* d_in, const int* in_sizes, int n_in,
                              void* d_out, int out_size)
{
    const int*   x;
    const float* W;
    int N;
    if (in_sizes[0] < in_sizes[1]) {
        x = (const int*)d_in[0];  W = (const float*)d_in[1];  N = in_sizes[0];
    } else {
        x = (const int*)d_in[1];  W = (const float*)d_in[0];  N = in_sizes[1];
    }
    int nchunks = (N + ROWS - 1) / ROWS;
    if (nchunks > NCHUNK) nchunks = NCHUNK;

    int setup_threads = NE * (NCHUNK / CB);          // 16416
    int setup_blocks  = (setup_threads + 255) / 256;
    pe_setup_kernel<<<setup_blocks, 256>>>(nchunks);

    pe_embed_kernel<<<nchunks, TPB>>>(x, W, (float*)d_out, N);
}

// round 5
// speedup vs baseline: 1.5731x; 1.0686x over previous
#include <cuda_runtime.h>

// out[n][d] = (x[n]==0 ? 0 : W[x[n]][d]) + PE(n,d)
// Even exponents e in {0,2,...,1024} -> 513 distinct frequencies (NE).
//
// Stage A (513 thr): w_e = 10000^{-e/D} in DP; row-rotation (sin,cos)(w_e).
// Stage B (525K thr): seed[c][ie] = (sin,cos)((128c+1)*w_e) via DP multiply +
//                     DP mod-2pi + MUFU __sincosf. Fully parallel, ~3us.
// Main: per 128-row chunk: seeds from L2 table, gather+add+store with G=8
//       load batching (79% DRAM). PE advances by fp32 rotation per row.

#define D_DIM   1024
#define TPB     256
#define ROWS    128
#define MAXN    131072
#define NCHUNK  (MAXN / ROWS)    // 1024
#define NE      513              // even exponents 0..1024
#define G       8                // rows batched per inner iteration

__device__ float2 g_seed[NCHUNK * NE];  // [c][ie] = (sin,cos)((128c+1)*w_e)
__device__ float2 g_rot[NE];            // [ie]    = (sin,cos)(w_e)
__device__ double g_w[NE];              // [ie]    = w_e (double)

__global__ void pe_setup_a(void)
{
    int ie = blockIdx.x * blockDim.x + threadIdx.x;
    if (ie >= NE) return;
    const double LOG1E4 = 9.210340371976184;       // ln(10000)
    double w = exp(-(double)(2 * ie) * (LOG1E4 / (double)D_DIM));
    g_w[ie] = w;
    double sw, cw;
    sincos(w, &sw, &cw);                           // small arg: fast path
    g_rot[ie] = make_float2((float)sw, (float)cw);
}

__global__ void pe_setup_b(int nchunks)
{
    int gid = blockIdx.x * blockDim.x + threadIdx.x;
    int total = nchunks * NE;
    if (gid >= total) return;
    int c  = gid / NE;
    int ie = gid - c * NE;

    const double TWO_PI  = 6.283185307179586476925287;
    const double INV_2PI = 0.15915494309189533576888;

    double w   = g_w[ie];
    double ang = (double)(c * ROWS + 1) * w;       // exact to ~3e-11 after mod
    ang -= TWO_PI * floor(ang * INV_2PI);
    float a = (float)ang;
    float ss, cc;
    __sincosf(a, &ss, &cc);                        // MUFU: ~1e-6 abs, plenty
    g_seed[gid] = make_float2(ss, cc);
}

__global__ __launch_bounds__(TPB, 3)
void pe_embed_kernel(const int* __restrict__ x,
                     const float* __restrict__ W,
                     float* __restrict__ out,
                     int N)
{
    __shared__ int sx[ROWS];

    const int chunk = blockIdx.x;
    const int n0 = chunk * ROWS;
    const int t  = threadIdx.x;

    if (t < ROWS) {
        int n = n0 + t;
        sx[t] = (n < N) ? x[n] : 0;
    }

    // states m=0..2 use exponent e = 4t + 2m -> table index ie = 2t + m
    float s[3], c[3], sw[3], cw[3];
    {
        const float2* __restrict__ seed = g_seed + (long)chunk * NE;
#pragma unroll
        for (int m = 0; m < 3; m++) {
            int ie = 2 * t + m;
            float2 sc = __ldg(&seed[ie]);
            float2 rt = __ldg(&g_rot[ie]);
            s[m] = sc.x;  c[m] = sc.y;
            sw[m] = rt.x; cw[m] = rt.y;
        }
    }
    __syncthreads();

    const float4* __restrict__ Wv = (const float4*)W;
    float4* outv = (float4*)out;

    const int nr = (N - n0 < ROWS) ? (N - n0) : ROWS;
    const long obase = (long)n0 * (D_DIM / 4) + t;

    if (nr == ROWS) {
        // fast path: batch G row-gathers before compute/store -> deep MLP
        for (int rb = 0; rb < ROWS; rb += G) {
            int   idx[G];
            float4 e[G];
#pragma unroll
            for (int j = 0; j < G; j++) idx[j] = sx[rb + j];
#pragma unroll
            for (int j = 0; j < G; j++)   // unconditional: row 0 is valid memory
                e[j] = __ldg(&Wv[(long)idx[j] * (D_DIM / 4) + t]);
#pragma unroll
            for (int j = 0; j < G; j++) {
                float msk = (idx[j] == 0) ? 0.f : 1.f;   // padding row -> zero
                float4 o;
                o.x = fmaf(e[j].x, msk, c[0]);
                o.y = fmaf(e[j].y, msk, s[1]);
                o.z = fmaf(e[j].z, msk, c[1]);
                o.w = fmaf(e[j].w, msk, s[2]);
                __stcs(&outv[obase + (long)(rb + j) * (D_DIM / 4)], o);
#pragma unroll
                for (int m = 0; m < 3; m++) {
                    float ns = fmaf(s[m], cw[m],  c[m] * sw[m]);
                    float nc = fmaf(c[m], cw[m], -s[m] * sw[m]);
                    s[m] = ns; c[m] = nc;
                }
            }
        }
    } else {
        for (int r = 0; r < nr; r++) {
            int idx = sx[r];
            float4 e = make_float4(0.f, 0.f, 0.f, 0.f);
            if (idx != 0) e = __ldg(&Wv[(long)idx * (D_DIM / 4) + t]);
            float4 o;
            o.x = e.x + c[0];
            o.y = e.y + s[1];
            o.z = e.z + c[1];
            o.w = e.w + s[2];
            __stcs(&outv[obase + (long)r * (D_DIM / 4)], o);
#pragma unroll
            for (int m = 0; m < 3; m++) {
                float ns = fmaf(s[m], cw[m],  c[m] * sw[m]);
                float nc = fmaf(c[m], cw[m], -s[m] * sw[m]);
                s[m] = ns; c[m] = nc;
            }
        }
    }
}

extern "C" void kernel_launch(void* const* d_in, const int* in_sizes, int n_in,
                              void* d_out, int out_size)
{
    const int*   x;
    const float* W;
    int N;
    if (in_sizes[0] < in_sizes[1]) {
        x = (const int*)d_in[0];  W = (const float*)d_in[1];  N = in_sizes[0];
    } else {
        x = (const int*)d_in[1];  W = (const float*)d_in[0];  N = in_sizes[1];
    }
    int nchunks = (N + ROWS - 1) / ROWS;
    if (nchunks > NCHUNK) nchunks = NCHUNK;

    pe_setup_a<<<(NE + 255) / 256, 256>>>();

    int total_b  = nchunks * NE;
    pe_setup_b<<<(total_b + 255) / 256, 256>>>(nchunks);

    pe_embed_kernel<<<nchunks, TPB>>>(x, W, (float*)d_out, N);
}